// round 8
// baseline (speedup 1.0000x reference)
#include <cuda_runtime.h>

// Problem constants (from reference)
#define B_  128
#define T_  32
#define D_  512
#define N4_ (B_ * T_ * D_ / 4)   // 524288 float4
#define D4_ (D_ / 4)             // 128

#define NBLK 256
#define NTHR 256
#define NTH  (NBLK * NTHR)       // 65536 threads; N4_/NTH == 8 exactly

// Persistent accumulators. Invariant: zero at kernel entry
// (zero at module load; last block resets via atomicExch each run).
__device__ float    g_acc[2] = {0.f, 0.f};
__device__ unsigned g_count  = 0u;

// out layout: [0]=sl_rhat [1]=sl_rbar [2]=temp_loss=0 [3]=r2_losses=0
//             [4..4+B*R)=r0 zeros, then r2 zeros.
__global__ void __launch_bounds__(NTHR, 2)
tidhy_reduce_kernel(const float4* __restrict__ X4,
                    const float4* __restrict__ bsd4,
                    float* __restrict__ out,
                    int out_size)
{
    const int tid = blockIdx.x * NTHR + threadIdx.x;

    // ---- single fully-front-batched group: 8 LDG.128 in flight/thread ----
    // stride NTH = 65536 is a multiple of D4_*T_ = 4096, so all 8 loads share
    //   d-index (float4) = tid & 127        -> single b_sd load
    //   timestep t       = (tid >> 7) & 31  -> warp-uniform predicate
    const float4 x0 = X4[tid];
    const float4 x1 = X4[tid + 1 * NTH];
    const float4 x2 = X4[tid + 2 * NTH];
    const float4 x3 = X4[tid + 3 * NTH];
    const float4 x4 = X4[tid + 4 * NTH];
    const float4 x5 = X4[tid + 5 * NTH];
    const float4 x6 = X4[tid + 6 * NTH];
    const float4 x7 = X4[tid + 7 * NTH];
    const float4 b  = bsd4[tid & (D4_ - 1)];

    // ---- zero-fill out[4 .. out_size) while X loads are in flight ----
    {
        const float4 z4 = make_float4(0.f, 0.f, 0.f, 0.f);
        float4* out4 = (float4*)(out + 4);          // byte offset 16: aligned
        const int n4 = (out_size - 4) >> 2;
        for (int i = tid; i < n4; i += NTH) out4[i] = z4;
        if (tid == 0)
            for (int i = 4 + (n4 << 2); i < out_size; ++i) out[i] = 0.f;
    }

    float s0 = (x0.x-b.x)*(x0.x-b.x) + (x0.y-b.y)*(x0.y-b.y)
             + (x0.z-b.z)*(x0.z-b.z) + (x0.w-b.w)*(x0.w-b.w);
    float s1 = (x1.x-b.x)*(x1.x-b.x) + (x1.y-b.y)*(x1.y-b.y)
             + (x1.z-b.z)*(x1.z-b.z) + (x1.w-b.w)*(x1.w-b.w);
    float s2 = (x2.x-b.x)*(x2.x-b.x) + (x2.y-b.y)*(x2.y-b.y)
             + (x2.z-b.z)*(x2.z-b.z) + (x2.w-b.w)*(x2.w-b.w);
    float s3 = (x3.x-b.x)*(x3.x-b.x) + (x3.y-b.y)*(x3.y-b.y)
             + (x3.z-b.z)*(x3.z-b.z) + (x3.w-b.w)*(x3.w-b.w);
    float s4 = (x4.x-b.x)*(x4.x-b.x) + (x4.y-b.y)*(x4.y-b.y)
             + (x4.z-b.z)*(x4.z-b.z) + (x4.w-b.w)*(x4.w-b.w);
    float s5 = (x5.x-b.x)*(x5.x-b.x) + (x5.y-b.y)*(x5.y-b.y)
             + (x5.z-b.z)*(x5.z-b.z) + (x5.w-b.w)*(x5.w-b.w);
    float s6 = (x6.x-b.x)*(x6.x-b.x) + (x6.y-b.y)*(x6.y-b.y)
             + (x6.z-b.z)*(x6.z-b.z) + (x6.w-b.w)*(x6.w-b.w);
    float s7 = (x7.x-b.x)*(x7.x-b.x) + (x7.y-b.y)*(x7.y-b.y)
             + (x7.z-b.z)*(x7.z-b.z) + (x7.w-b.w)*(x7.w-b.w);
    float v = ((s0 + s1) + (s2 + s3)) + ((s4 + s5) + (s6 + s7));

    // ---- warp reduction (t0 predicate is warp-uniform) ----
    #pragma unroll
    for (int o = 16; o > 0; o >>= 1)
        v += __shfl_xor_sync(0xffffffffu, v, o);

    __shared__ float sh_a[8], sh_t[8];
    const int lane = threadIdx.x & 31;
    const int wid  = threadIdx.x >> 5;
    const bool is_t0 = (((tid >> 7) & (T_ - 1)) == 0);   // warp-uniform
    if (lane == 0) { sh_a[wid] = v; sh_t[wid] = is_t0 ? v : 0.f; }
    __syncthreads();

    if (wid == 0) {
        float a = (lane < (NTHR >> 5)) ? sh_a[lane] : 0.f;
        float t = (lane < (NTHR >> 5)) ? sh_t[lane] : 0.f;
        #pragma unroll
        for (int o = 4; o > 0; o >>= 1) {
            a += __shfl_xor_sync(0xffffffffu, a, o);
            t += __shfl_xor_sync(0xffffffffu, t, o);
        }
        if (lane == 0) {
            atomicAdd(&g_acc[0], a);          // sum over all t
            atomicAdd(&g_acc[1], a - t);      // sum over t >= 1
            __threadfence();
            unsigned old = atomicInc(&g_count, NBLK - 1);  // wraps to 0
            if (old == NBLK - 1) {
                float tot_all = atomicExch(&g_acc[0], 0.f); // read+reset
                float tot_r   = atomicExch(&g_acc[1], 0.f);
                *(float4*)out = make_float4(tot_all * (1.0f / (float)B_),
                                            tot_r   * (1.0f / (float)B_),
                                            0.f, 0.f);
            }
        }
    }
}

extern "C" void kernel_launch(void* const* d_in, const int* in_sizes, int n_in,
                              void* d_out, int out_size)
{
    const float4* X4   = (const float4*)d_in[0];
    const float4* bsd4 = (const float4*)d_in[3];
    float* out = (float*)d_out;
    tidhy_reduce_kernel<<<NBLK, NTHR>>>(X4, bsd4, out, out_size);
}

// round 14
// speedup vs baseline: 1.0772x; 1.0772x over previous
#include <cuda_runtime.h>

// Problem constants (from reference)
#define B_  128
#define T_  32
#define D_  512
#define N4_ (B_ * T_ * D_ / 4)   // 524288 float4
#define D4_ (D_ / 4)             // 128

#define NBLK 128
#define NTHR 256
#define NTH  (NBLK * NTHR)       // 32768 threads; N4_/NTH == 16 exactly

// Persistent accumulators. Invariant: zero at kernel entry
// (zero at module load; last block resets via atomicExch each run).
__device__ float    g_acc[2] = {0.f, 0.f};
__device__ unsigned g_count  = 0u;

// NOTE: parameter named P (not x!) so member accessors .x/.y/.z/.w survive
// preprocessing intact.
#define SQ4(P) (((P).x-b.x)*((P).x-b.x) + ((P).y-b.y)*((P).y-b.y) + \
                ((P).z-b.z)*((P).z-b.z) + ((P).w-b.w)*((P).w-b.w))

// out layout: [0]=sl_rhat [1]=sl_rbar [2]=temp_loss=0 [3]=r2_losses=0
//             [4..4+B*R)=r0 zeros, then r2 zeros.
__global__ void __launch_bounds__(NTHR, 1)
tidhy_reduce_kernel(const float4* __restrict__ X4,
                    const float4* __restrict__ bsd4,
                    float* __restrict__ out,
                    int out_size)
{
    const int tid = blockIdx.x * NTHR + threadIdx.x;

    // ---- one flat front-batched group: 16 LDG.128 in flight per thread ----
    // stride NTH = 32768 is a multiple of D4_*T_ = 4096, so all 16 loads share
    //   d-index (float4) = tid & 127        -> single b_sd load
    //   timestep t       = (tid >> 7) & 31  -> warp-uniform predicate
    const float4 x0  = X4[tid];
    const float4 x1  = X4[tid +  1 * NTH];
    const float4 x2  = X4[tid +  2 * NTH];
    const float4 x3  = X4[tid +  3 * NTH];
    const float4 x4  = X4[tid +  4 * NTH];
    const float4 x5  = X4[tid +  5 * NTH];
    const float4 x6  = X4[tid +  6 * NTH];
    const float4 x7  = X4[tid +  7 * NTH];
    const float4 x8  = X4[tid +  8 * NTH];
    const float4 x9  = X4[tid +  9 * NTH];
    const float4 x10 = X4[tid + 10 * NTH];
    const float4 x11 = X4[tid + 11 * NTH];
    const float4 x12 = X4[tid + 12 * NTH];
    const float4 x13 = X4[tid + 13 * NTH];
    const float4 x14 = X4[tid + 14 * NTH];
    const float4 x15 = X4[tid + 15 * NTH];
    const float4 b   = bsd4[tid & (D4_ - 1)];

    // ---- zero-fill out[4 .. out_size) while X loads are in flight ----
    // n4 = 12284-ish < NTH: at most one float4 store per thread.
    {
        const float4 z4 = make_float4(0.f, 0.f, 0.f, 0.f);
        float4* out4 = (float4*)(out + 4);          // byte offset 16: aligned
        const int n4 = (out_size - 4) >> 2;
        for (int i = tid; i < n4; i += NTH) out4[i] = z4;
        if (tid == 0)
            for (int i = 4 + (n4 << 2); i < out_size; ++i) out[i] = 0.f;
    }

    float s0 = SQ4(x0),  s1 = SQ4(x1),  s2 = SQ4(x2),  s3 = SQ4(x3);
    float s4 = SQ4(x4),  s5 = SQ4(x5),  s6 = SQ4(x6),  s7 = SQ4(x7);
    float s8 = SQ4(x8),  s9 = SQ4(x9),  sA = SQ4(x10), sB = SQ4(x11);
    float sC = SQ4(x12), sD = SQ4(x13), sE = SQ4(x14), sF = SQ4(x15);
    float v = (((s0 + s1) + (s2 + s3)) + ((s4 + s5) + (s6 + s7)))
            + (((s8 + s9) + (sA + sB)) + ((sC + sD) + (sE + sF)));

    // ---- warp reduction (t0 predicate is warp-uniform) ----
    #pragma unroll
    for (int o = 16; o > 0; o >>= 1)
        v += __shfl_xor_sync(0xffffffffu, v, o);

    __shared__ float sh_a[8], sh_t[8];
    const int lane = threadIdx.x & 31;
    const int wid  = threadIdx.x >> 5;
    const bool is_t0 = (((tid >> 7) & (T_ - 1)) == 0);   // warp-uniform
    if (lane == 0) { sh_a[wid] = v; sh_t[wid] = is_t0 ? v : 0.f; }
    __syncthreads();

    if (wid == 0) {
        float a = (lane < (NTHR >> 5)) ? sh_a[lane] : 0.f;
        float t = (lane < (NTHR >> 5)) ? sh_t[lane] : 0.f;
        #pragma unroll
        for (int o = 4; o > 0; o >>= 1) {
            a += __shfl_xor_sync(0xffffffffu, a, o);
            t += __shfl_xor_sync(0xffffffffu, t, o);
        }
        if (lane == 0) {
            atomicAdd(&g_acc[0], a);          // sum over all t
            atomicAdd(&g_acc[1], a - t);      // sum over t >= 1
            __threadfence();
            unsigned old = atomicInc(&g_count, NBLK - 1);  // wraps to 0
            if (old == NBLK - 1) {
                float tot_all = atomicExch(&g_acc[0], 0.f); // read+reset
                float tot_r   = atomicExch(&g_acc[1], 0.f);
                *(float4*)out = make_float4(tot_all * (1.0f / (float)B_),
                                            tot_r   * (1.0f / (float)B_),
                                            0.f, 0.f);
            }
        }
    }
}

extern "C" void kernel_launch(void* const* d_in, const int* in_sizes, int n_in,
                              void* d_out, int out_size)
{
    const float4* X4   = (const float4*)d_in[0];
    const float4* bsd4 = (const float4*)d_in[3];
    float* out = (float*)d_out;
    tidhy_reduce_kernel<<<NBLK, NTHR>>>(X4, bsd4, out, out_size);
}